// round 12
// baseline (speedup 1.0000x reference)
#include <cuda_runtime.h>

// 3-layer LSTM (IN=5, H=50) + FC(50->1), B=1024, T=512.
// v11: layer-pipelined, warp-pure, J-PAIR threads (2 hidden units/thread).
//   G1 (warps 0-3):  L1 @ t=ph.  100 gate thr (25 jp x 4 ks) + 28 spares.
//   G2 (warps 4-7):  L2 @ t=ph-1. 100 gate thr.
//   G3 (warps 8-11): L3 @ t=ph-2. 100 gate thr.
// Thread (jp, ks) accumulates units {jp, jp+25} x 4 gates x 4 batch-pairs
// (64 acc regs, 32 independent FFMA2 chains) over k = ks+4i. 384 threads ->
// reg cap 170, no spill. v-loads are 8-way broadcast (address dep on ks
// only); w-loads conflict-free (WROW=200: windows 4(2ks+jp+{0,1}) mod 32).
// Pairwise named barriers as v10. No dynamic register indexing anywhere.

#define T_STEPS   512
#define IN_DIM    5
#define HID       50
#define NB        7
#define NTHREADS  384
#define GRID      148
#define WROW      200

// smem offsets (floats)
enum {
    W1_OFF = 0,                 // 56 k-rows * 200 = 11200
    W2_OFF = 11200,             // 100 * 200 = 20000
    W3_OFF = 31200,             // 20000
    V1_OFF = 51200,             // 2 bufs * 56 rows * 8  [x(0-4),pad5,h1(6-55)]
    V2_OFF = 52096,             // 2 bufs * 100 * 8      [h1,h2]
    V3_OFF = 53696,             // 1600                  [h2,h3]
    SH_FLOATS = 55296           // 221184 bytes
};
#define V1B 448
#define V2B 800

typedef unsigned long long ull;

__device__ __forceinline__ ull ffma2(ull a, ull b, ull c) {
    ull d;
    asm("fma.rn.f32x2 %0, %1, %2, %3;" : "=l"(d) : "l"(a), "l"(b), "l"(c));
    return d;
}
__device__ __forceinline__ ull add2(ull a, ull b) {
    ull d;
    asm("add.rn.f32x2 %0, %1, %2;" : "=l"(d) : "l"(a), "l"(b));
    return d;
}
__device__ __forceinline__ ull pack2(float w) {
    ull d;
    asm("mov.b64 %0, {%1, %1};" : "=l"(d) : "f"(w));
    return d;
}
__device__ __forceinline__ void unpk(ull a, float& lo, float& hi) {
    asm("mov.b64 {%0, %1}, %2;" : "=f"(lo), "=f"(hi) : "l"(a));
}
__device__ __forceinline__ float fast_ex2(float x) {
    float y; asm("ex2.approx.ftz.f32 %0, %1;" : "=f"(y) : "f"(x)); return y;
}
__device__ __forceinline__ float fast_rcp(float x) {
    float y; asm("rcp.approx.ftz.f32 %0, %1;" : "=f"(y) : "f"(x)); return y;
}
__device__ __forceinline__ float sigm(float x) {
    return fast_rcp(1.0f + fast_ex2(-1.4426950408889634f * x));
}
__device__ __forceinline__ float tanh_acc(float x) {
    float r = fast_rcp(1.0f + fast_ex2(-2.8853900817779268f * x));
    return r + r - 1.0f;
}

// Accumulate units {jp, jp+25} x 4 gates x 4 batch-pairs over k = ks + 4i.
template<int NK>
__device__ __forceinline__ void accum2(const float* __restrict__ shw,
                                       const float* __restrict__ vrd,
                                       int jp, int ks,
                                       ull accA[4][4], ull accB[4][4]) {
#pragma unroll
    for (int g = 0; g < 4; g++)
#pragma unroll
        for (int bp = 0; bp < 4; bp++) { accA[g][bp] = 0ull; accB[g][bp] = 0ull; }

#pragma unroll
    for (int i = 0; i < NK; i++) {
        const int k = ks + 4 * i;
        const float* wr = shw + k * WROW + 4 * jp;
        const float4 wA = *reinterpret_cast<const float4*>(wr);         // unit jp
        const float4 wB = *reinterpret_cast<const float4*>(wr + 100);   // unit jp+25
        const ulonglong2 va = *reinterpret_cast<const ulonglong2*>(vrd + k * 8);
        const ulonglong2 vb = *reinterpret_cast<const ulonglong2*>(vrd + k * 8 + 4);
        ull a0 = pack2(wA.x), a1 = pack2(wA.y), a2 = pack2(wA.z), a3 = pack2(wA.w);
        ull b0 = pack2(wB.x), b1 = pack2(wB.y), b2 = pack2(wB.z), b3 = pack2(wB.w);
        accA[0][0] = ffma2(a0, va.x, accA[0][0]);
        accA[0][1] = ffma2(a0, va.y, accA[0][1]);
        accA[0][2] = ffma2(a0, vb.x, accA[0][2]);
        accA[0][3] = ffma2(a0, vb.y, accA[0][3]);
        accA[1][0] = ffma2(a1, va.x, accA[1][0]);
        accA[1][1] = ffma2(a1, va.y, accA[1][1]);
        accA[1][2] = ffma2(a1, vb.x, accA[1][2]);
        accA[1][3] = ffma2(a1, vb.y, accA[1][3]);
        accA[2][0] = ffma2(a2, va.x, accA[2][0]);
        accA[2][1] = ffma2(a2, va.y, accA[2][1]);
        accA[2][2] = ffma2(a2, vb.x, accA[2][2]);
        accA[2][3] = ffma2(a2, vb.y, accA[2][3]);
        accA[3][0] = ffma2(a3, va.x, accA[3][0]);
        accA[3][1] = ffma2(a3, va.y, accA[3][1]);
        accA[3][2] = ffma2(a3, vb.x, accA[3][2]);
        accA[3][3] = ffma2(a3, vb.y, accA[3][3]);
        accB[0][0] = ffma2(b0, va.x, accB[0][0]);
        accB[0][1] = ffma2(b0, va.y, accB[0][1]);
        accB[0][2] = ffma2(b0, vb.x, accB[0][2]);
        accB[0][3] = ffma2(b0, vb.y, accB[0][3]);
        accB[1][0] = ffma2(b1, va.x, accB[1][0]);
        accB[1][1] = ffma2(b1, va.y, accB[1][1]);
        accB[1][2] = ffma2(b1, vb.x, accB[1][2]);
        accB[1][3] = ffma2(b1, vb.y, accB[1][3]);
        accB[2][0] = ffma2(b2, va.x, accB[2][0]);
        accB[2][1] = ffma2(b2, va.y, accB[2][1]);
        accB[2][2] = ffma2(b2, vb.x, accB[2][2]);
        accB[2][3] = ffma2(b2, vb.y, accB[2][3]);
        accB[3][0] = ffma2(b3, va.x, accB[3][0]);
        accB[3][1] = ffma2(b3, va.y, accB[3][1]);
        accB[3][2] = ffma2(b3, vb.x, accB[3][2]);
        accB[3][3] = ffma2(b3, vb.y, accB[3][3]);
    }
}

// 4-way K butterfly (payload-halving); thread ks ends with batches 2ks,2ks+1.
__device__ __forceinline__ void reduce_quad(const ull acc[4][4], int ks,
                                            unsigned qmask, const float bz[4],
                                            float ta[4], float tb[4]) {
    const bool k1 = (ks & 2) != 0;
    const bool k0 = (ks & 1) != 0;
#pragma unroll
    for (int g = 0; g < 4; g++) {
        ull s0 = k1 ? acc[g][0] : acc[g][2];
        ull s1 = k1 ? acc[g][1] : acc[g][3];
        ull K0 = k1 ? acc[g][2] : acc[g][0];
        ull K1 = k1 ? acc[g][3] : acc[g][1];
        ull m0 = add2(K0, __shfl_xor_sync(qmask, s0, 2));
        ull m1 = add2(K1, __shfl_xor_sync(qmask, s1, 2));
        ull s  = k0 ? m0 : m1;
        ull K  = k0 ? m1 : m0;
        ull tot = add2(K, __shfl_xor_sync(qmask, s, 1));
        float lo, hi; unpk(tot, lo, hi);
        ta[g] = lo + bz[g];
        tb[g] = hi + bz[g];
    }
}

__device__ __forceinline__ float2 update2(const float ta[4], const float tb[4],
                                          float c[2]) {
    float ha, hb;
    {
        float iv = sigm(ta[0]), fv = sigm(ta[1]);
        float gv = tanh_acc(ta[2]), ov = sigm(ta[3]);
        c[0] = fv * c[0] + iv * gv;
        ha = ov * tanh_acc(c[0]);
    }
    {
        float iv = sigm(tb[0]), fv = sigm(tb[1]);
        float gv = tanh_acc(tb[2]), ov = sigm(tb[3]);
        c[1] = fv * c[1] + iv * gv;
        hb = ov * tanh_acc(c[1]);
    }
    return make_float2(ha, hb);
}

// One layer phase for a j-pair thread. wr1/wr2: write bases for unit jp
// (unit jp+25 = +200 floats = +25 rows).
template<int NK, bool HAS2>
__device__ __forceinline__ void layer_phase_jp(float* sh,
                                               const float* __restrict__ shw,
                                               const float* __restrict__ vrd,
                                               int jp, int ks, unsigned qmask,
                                               const float bzA[4],
                                               const float bzB[4],
                                               float cA[2], float cB[2],
                                               int wr1, int wr2) {
    ull accA[4][4], accB[4][4];
    accum2<NK>(shw, vrd, jp, ks, accA, accB);

    float ta[4], tb[4];
    reduce_quad(accA, ks, qmask, bzA, ta, tb);
    float2 hA = update2(ta, tb, cA);
    reduce_quad(accB, ks, qmask, bzB, ta, tb);
    float2 hB = update2(ta, tb, cB);

    *reinterpret_cast<float2*>(sh + wr1 + 2 * ks)       = hA;
    *reinterpret_cast<float2*>(sh + wr1 + 200 + 2 * ks) = hB;
    if (HAS2) {
        *reinterpret_cast<float2*>(sh + wr2 + 2 * ks)       = hA;
        *reinterpret_cast<float2*>(sh + wr2 + 200 + 2 * ks) = hB;
    }
}

__global__ void __launch_bounds__(NTHREADS, 1)
lstm3_pipe_kernel(const float* __restrict__ x,
                  const float* __restrict__ Wih1, const float* __restrict__ Whh1,
                  const float* __restrict__ bih1, const float* __restrict__ bhh1,
                  const float* __restrict__ Wih2, const float* __restrict__ Whh2,
                  const float* __restrict__ bih2, const float* __restrict__ bhh2,
                  const float* __restrict__ Wih3, const float* __restrict__ Whh3,
                  const float* __restrict__ bih3, const float* __restrict__ bhh3,
                  const float* __restrict__ fcW, const float* __restrict__ fcb,
                  float* __restrict__ out) {
    extern __shared__ float sh[];
    const int tid = threadIdx.x;
    const int bid = blockIdx.x;
    const int lane = tid & 31;
    const int wid = tid >> 5;

    int b0, cnt;
    if (bid < 136) { b0 = bid * 7;               cnt = 7; }
    else           { b0 = 952 + (bid - 136) * 6; cnt = 6; }

    // zero v buffers
    for (int i = V1_OFF + tid; i < SH_FLOATS; i += NTHREADS) sh[i] = 0.0f;

    // stage W1: [k][j*4+g]; k<5 = Wih1, k=5 pad0, k>=6 = Whh1
    for (int idx = tid; idx < 200 * 56; idx += NTHREADS) {
        int gr = idx / 56, k = idx - gr * 56;
        int g = gr / 50, j = gr - g * 50;
        float v;
        if (k < IN_DIM)       v = Wih1[gr * IN_DIM + k];
        else if (k == IN_DIM) v = 0.0f;
        else                  v = Whh1[gr * HID + (k - 6)];
        sh[W1_OFF + k * WROW + j * 4 + g] = v;
    }
    for (int idx = tid; idx < 200 * 100; idx += NTHREADS) {
        int gr = idx / 100, k = idx - gr * 100;
        int g = gr / 50, j = gr - g * 50;
        float v = (k < HID) ? Wih2[gr * HID + k] : Whh2[gr * HID + (k - HID)];
        sh[W2_OFF + k * WROW + j * 4 + g] = v;
    }
    for (int idx = tid; idx < 200 * 100; idx += NTHREADS) {
        int gr = idx / 100, k = idx - gr * 100;
        int g = gr / 50, j = gr - g * 50;
        float v = (k < HID) ? Wih3[gr * HID + k] : Whh3[gr * HID + (k - HID)];
        sh[W3_OFF + k * WROW + j * 4 + g] = v;
    }
    // x(t=0) into v1 buf0
    if (tid < NB * IN_DIM) {
        int b = tid / IN_DIM, d = tid - b * IN_DIM;
        if (b < cnt)
            sh[V1_OFF + d * 8 + b] = x[(size_t)(b0 + b) * T_STEPS * IN_DIM + d];
    }

    // ---- groups: 3 x 4 warps ----
    const int gi  = tid & 127;            // index within group
    const bool isGate = (gi < 100);
    const int jp = gi >> 2;
    const int ks = gi & 3;
    const unsigned qmask = 0xFu << (lane & ~3);

    float bzA[4] = {0.f, 0.f, 0.f, 0.f};
    float bzB[4] = {0.f, 0.f, 0.f, 0.f};
    if (isGate) {
        const float *bi, *bh;
        if (wid < 4)      { bi = bih1; bh = bhh1; }
        else if (wid < 8) { bi = bih2; bh = bhh2; }
        else              { bi = bih3; bh = bhh3; }
#pragma unroll
        for (int g = 0; g < 4; g++) {
            bzA[g] = bi[g * HID + jp]      + bh[g * HID + jp];
            bzB[g] = bi[g * HID + jp + 25] + bh[g * HID + jp + 25];
        }
    }
    float cA[2] = {0.f, 0.f}, cB[2] = {0.f, 0.f};

    const int sp_i = tid - 100;           // G1 spares: tid 100-127
    __syncthreads();   // weights + v init visible

    for (int ph = 0; ph < T_STEPS + 2; ph++) {
        const int p = ph & 1, q = p ^ 1;

        if (wid < 4) {              // G1: layer1 @ t=ph (+ x prefetch)
            if (isGate) {
                if (ph < T_STEPS)
                    layer_phase_jp<14, true>(sh, sh + W1_OFF,
                                             sh + V1_OFF + p * V1B,
                                             jp, ks, qmask, bzA, bzB, cA, cB,
                                             V1_OFF + q * V1B + (6 + jp) * 8,
                                             V2_OFF + q * V2B + jp * 8);
            } else {
                if (ph + 1 < T_STEPS) {
#pragma unroll
                    for (int r = 0; r < 2; r++) {
                        int s0 = sp_i + 28 * r;
                        if (s0 < NB * IN_DIM) {
                            int bb = s0 / IN_DIM, dd = s0 - bb * IN_DIM;
                            if (bb < cnt)
                                sh[V1_OFF + q * V1B + dd * 8 + bb] =
                                    x[(size_t)(b0 + bb) * T_STEPS * IN_DIM
                                      + (ph + 1) * IN_DIM + dd];
                        }
                    }
                }
            }
            asm volatile("bar.sync 1, 256;" ::: "memory");
        } else if (wid < 8) {       // G2: layer2 @ t=ph-1
            if (isGate && ph >= 1 && ph <= T_STEPS)
                layer_phase_jp<25, true>(sh, sh + W2_OFF,
                                         sh + V2_OFF + p * V2B,
                                         jp, ks, qmask, bzA, bzB, cA, cB,
                                         V2_OFF + q * V2B + (50 + jp) * 8,
                                         V3_OFF + q * V2B + jp * 8);
            asm volatile("bar.sync 1, 256;" ::: "memory");
            asm volatile("bar.sync 2, 256;" ::: "memory");
        } else {                    // G3: layer3 @ t=ph-2
            if (isGate && ph >= 2)
                layer_phase_jp<25, false>(sh, sh + W3_OFF,
                                          sh + V3_OFF + p * V2B,
                                          jp, ks, qmask, bzA, bzB, cA, cB,
                                          V3_OFF + q * V2B + (50 + jp) * 8, 0);
            asm volatile("bar.sync 2, 256;" ::: "memory");
        }
    }
    __syncthreads();

    // FC: h3(511) computed at ph=513 -> parity q=0; row 50+j, column b
    if (tid < cnt) {
        float a = fcb[0];
#pragma unroll
        for (int jj = 0; jj < HID; jj++)
            a += fcW[jj] * sh[V3_OFF + (50 + jj) * 8 + tid];
        out[b0 + tid] = a;
    }
}

extern "C" void kernel_launch(void* const* d_in, const int* in_sizes, int n_in,
                              void* d_out, int out_size) {
    const float* x    = (const float*)d_in[0];
    const float* Wih1 = (const float*)d_in[1];
    const float* Whh1 = (const float*)d_in[2];
    const float* bih1 = (const float*)d_in[3];
    const float* bhh1 = (const float*)d_in[4];
    const float* Wih2 = (const float*)d_in[5];
    const float* Whh2 = (const float*)d_in[6];
    const float* bih2 = (const float*)d_in[7];
    const float* bhh2 = (const float*)d_in[8];
    const float* Wih3 = (const float*)d_in[9];
    const float* Whh3 = (const float*)d_in[10];
    const float* bih3 = (const float*)d_in[11];
    const float* bhh3 = (const float*)d_in[12];
    const float* fcW  = (const float*)d_in[13];
    const float* fcb  = (const float*)d_in[14];

    size_t shbytes = (size_t)SH_FLOATS * sizeof(float);
    cudaFuncSetAttribute(lstm3_pipe_kernel,
                         cudaFuncAttributeMaxDynamicSharedMemorySize,
                         (int)shbytes);
    lstm3_pipe_kernel<<<GRID, NTHREADS, shbytes>>>(
        x, Wih1, Whh1, bih1, bhh1, Wih2, Whh2, bih2, bhh2,
        Wih3, Whh3, bih3, bhh3, fcW, fcb, (float*)d_out);
}

// round 13
// speedup vs baseline: 1.1072x; 1.1072x over previous
#include <cuda_runtime.h>

// 3-layer LSTM (IN=5, H=50) + FC(50->1), B=1024, T=512.
// v12 = v9/v10 machinery with 3 UNIFORM groups of 200 gate threads
// (4-way K-split everywhere, incl. L1) -> 672 threads = 21 warps.
//   G1 (warps 0-6):   L1 @ t=ph   (NK=14 over 56-row W1) + x prefetch
//   G2 (warps 7-13):  L2 @ t=ph-1 (NK=25)
//   G3 (warps 14-20): L3 @ t=ph-2 (NK=25)
// Batch-packed f32x2 accumulators (acc[4][4] = 32 regs; reg cap 96 at 672
// threads = exactly what v9 compiled to). Pairwise named barriers:
// bar1 (448: G1+G2), bar2 (448: G2+G3). No dynamic register indexing.

#define T_STEPS   512
#define IN_DIM    5
#define HID       50
#define NB        7
#define NTHREADS  672
#define GRID      148
#define WROW      200

// smem offsets (floats)
enum {
    W1_OFF = 0,                 // 56 k-rows * 200 = 11200
    W2_OFF = 11200,             // 100 * 200 = 20000
    W3_OFF = 31200,             // 20000
    V1_OFF = 51200,             // 2 bufs * 56 rows * 8  [x(0-4),pad5,h1(6-55)]
    V2_OFF = 52096,             // 2 bufs * 100 * 8      [h1,h2]
    V3_OFF = 53696,             // 1600                  [h2,h3]
    SH_FLOATS = 55296           // 221184 bytes
};
#define V1B 448
#define V2B 800

typedef unsigned long long ull;

__device__ __forceinline__ ull ffma2(ull a, ull b, ull c) {
    ull d;
    asm("fma.rn.f32x2 %0, %1, %2, %3;" : "=l"(d) : "l"(a), "l"(b), "l"(c));
    return d;
}
__device__ __forceinline__ ull add2(ull a, ull b) {
    ull d;
    asm("add.rn.f32x2 %0, %1, %2;" : "=l"(d) : "l"(a), "l"(b));
    return d;
}
__device__ __forceinline__ ull pack2(float w) {
    ull d;
    asm("mov.b64 %0, {%1, %1};" : "=l"(d) : "f"(w));
    return d;
}
__device__ __forceinline__ void unpk(ull a, float& lo, float& hi) {
    asm("mov.b64 {%0, %1}, %2;" : "=f"(lo), "=f"(hi) : "l"(a));
}
__device__ __forceinline__ float fast_ex2(float x) {
    float y; asm("ex2.approx.ftz.f32 %0, %1;" : "=f"(y) : "f"(x)); return y;
}
__device__ __forceinline__ float fast_rcp(float x) {
    float y; asm("rcp.approx.ftz.f32 %0, %1;" : "=f"(y) : "f"(x)); return y;
}
__device__ __forceinline__ float sigm(float x) {
    return fast_rcp(1.0f + fast_ex2(-1.4426950408889634f * x));
}
__device__ __forceinline__ float tanh_acc(float x) {
    float r = fast_rcp(1.0f + fast_ex2(-2.8853900817779268f * x));
    return r + r - 1.0f;
}

// Accumulate 4 gates x 4 batch-pairs over k = ks + 4*i, i < NK.
template<int NK>
__device__ __forceinline__ void accum(const float* __restrict__ shw,
                                      const float* __restrict__ vrd,
                                      int j, int ks, ull acc[4][4]) {
#pragma unroll
    for (int g = 0; g < 4; g++)
#pragma unroll
        for (int bp = 0; bp < 4; bp++) acc[g][bp] = 0ull;

#pragma unroll
    for (int i = 0; i < NK; i++) {
        const int k = ks + 4 * i;
        const float4 w = *reinterpret_cast<const float4*>(shw + k * WROW + 4 * j);
        const ulonglong2 va = *reinterpret_cast<const ulonglong2*>(vrd + k * 8);
        const ulonglong2 vb = *reinterpret_cast<const ulonglong2*>(vrd + k * 8 + 4);
        ull w0 = pack2(w.x), w1 = pack2(w.y), w2 = pack2(w.z), w3 = pack2(w.w);
        acc[0][0] = ffma2(w0, va.x, acc[0][0]);
        acc[0][1] = ffma2(w0, va.y, acc[0][1]);
        acc[0][2] = ffma2(w0, vb.x, acc[0][2]);
        acc[0][3] = ffma2(w0, vb.y, acc[0][3]);
        acc[1][0] = ffma2(w1, va.x, acc[1][0]);
        acc[1][1] = ffma2(w1, va.y, acc[1][1]);
        acc[1][2] = ffma2(w1, vb.x, acc[1][2]);
        acc[1][3] = ffma2(w1, vb.y, acc[1][3]);
        acc[2][0] = ffma2(w2, va.x, acc[2][0]);
        acc[2][1] = ffma2(w2, va.y, acc[2][1]);
        acc[2][2] = ffma2(w2, vb.x, acc[2][2]);
        acc[2][3] = ffma2(w2, vb.y, acc[2][3]);
        acc[3][0] = ffma2(w3, va.x, acc[3][0]);
        acc[3][1] = ffma2(w3, va.y, acc[3][1]);
        acc[3][2] = ffma2(w3, vb.x, acc[3][2]);
        acc[3][3] = ffma2(w3, vb.y, acc[3][3]);
    }
}

// Layer phase: 4-way K-split, payload-halving ull butterfly, c/h update for
// batches 2ks and 2ks+1, h written to 1-2 destinations.
template<int NK, bool HAS2>
__device__ __forceinline__ void layer_phase(float* sh,
                                            const float* __restrict__ shw,
                                            const float* __restrict__ vrd,
                                            int j, int ks, unsigned qmask,
                                            const float bz[4],
                                            float& ca, float& cb,
                                            int wr1, int wr2) {
    ull acc[4][4];
    accum<NK>(shw, vrd, j, ks, acc);

    const bool k1 = (ks & 2) != 0;
    const bool k0 = (ks & 1) != 0;
    float ta[4], tb[4];
#pragma unroll
    for (int g = 0; g < 4; g++) {
        ull s0 = k1 ? acc[g][0] : acc[g][2];
        ull s1 = k1 ? acc[g][1] : acc[g][3];
        ull K0 = k1 ? acc[g][2] : acc[g][0];
        ull K1 = k1 ? acc[g][3] : acc[g][1];
        ull m0 = add2(K0, __shfl_xor_sync(qmask, s0, 2));
        ull m1 = add2(K1, __shfl_xor_sync(qmask, s1, 2));
        ull s  = k0 ? m0 : m1;
        ull K  = k0 ? m1 : m0;
        ull tot = add2(K, __shfl_xor_sync(qmask, s, 1));
        float lo, hi; unpk(tot, lo, hi);
        ta[g] = lo + bz[g];
        tb[g] = hi + bz[g];
    }
    float ha, hb;
    {
        float iv = sigm(ta[0]), fv = sigm(ta[1]);
        float gv = tanh_acc(ta[2]), ov = sigm(ta[3]);
        ca = fv * ca + iv * gv;
        ha = ov * tanh_acc(ca);
    }
    {
        float iv = sigm(tb[0]), fv = sigm(tb[1]);
        float gv = tanh_acc(tb[2]), ov = sigm(tb[3]);
        cb = fv * cb + iv * gv;
        hb = ov * tanh_acc(cb);
    }
    float2 hh = make_float2(ha, hb);
    *reinterpret_cast<float2*>(sh + wr1 + 2 * ks) = hh;
    if (HAS2) *reinterpret_cast<float2*>(sh + wr2 + 2 * ks) = hh;
}

__global__ void __launch_bounds__(NTHREADS, 1)
lstm3_pipe_kernel(const float* __restrict__ x,
                  const float* __restrict__ Wih1, const float* __restrict__ Whh1,
                  const float* __restrict__ bih1, const float* __restrict__ bhh1,
                  const float* __restrict__ Wih2, const float* __restrict__ Whh2,
                  const float* __restrict__ bih2, const float* __restrict__ bhh2,
                  const float* __restrict__ Wih3, const float* __restrict__ Whh3,
                  const float* __restrict__ bih3, const float* __restrict__ bhh3,
                  const float* __restrict__ fcW, const float* __restrict__ fcb,
                  float* __restrict__ out) {
    extern __shared__ float sh[];
    const int tid = threadIdx.x;
    const int bid = blockIdx.x;
    const int lane = tid & 31;
    const int wid = tid >> 5;

    int b0, cnt;
    if (bid < 136) { b0 = bid * 7;               cnt = 7; }
    else           { b0 = 952 + (bid - 136) * 6; cnt = 6; }

    // zero v buffers
    for (int i = V1_OFF + tid; i < SH_FLOATS; i += NTHREADS) sh[i] = 0.0f;

    // stage W1: [k][j*4+g]; k<5 = Wih1, k=5 pad0, k>=6 = Whh1
    for (int idx = tid; idx < 200 * 56; idx += NTHREADS) {
        int gr = idx / 56, k = idx - gr * 56;
        int g = gr / 50, j = gr - g * 50;
        float v;
        if (k < IN_DIM)       v = Wih1[gr * IN_DIM + k];
        else if (k == IN_DIM) v = 0.0f;
        else                  v = Whh1[gr * HID + (k - 6)];
        sh[W1_OFF + k * WROW + j * 4 + g] = v;
    }
    for (int idx = tid; idx < 200 * 100; idx += NTHREADS) {
        int gr = idx / 100, k = idx - gr * 100;
        int g = gr / 50, j = gr - g * 50;
        float v = (k < HID) ? Wih2[gr * HID + k] : Whh2[gr * HID + (k - HID)];
        sh[W2_OFF + k * WROW + j * 4 + g] = v;
    }
    for (int idx = tid; idx < 200 * 100; idx += NTHREADS) {
        int gr = idx / 100, k = idx - gr * 100;
        int g = gr / 50, j = gr - g * 50;
        float v = (k < HID) ? Wih3[gr * HID + k] : Whh3[gr * HID + (k - HID)];
        sh[W3_OFF + k * WROW + j * 4 + g] = v;
    }
    // x(t=0) into v1 buf0
    if (tid < NB * IN_DIM) {
        int b = tid / IN_DIM, d = tid - b * IN_DIM;
        if (b < cnt)
            sh[V1_OFF + d * 8 + b] = x[(size_t)(b0 + b) * T_STEPS * IN_DIM + d];
    }

    // ---- groups: 3 x 7 warps, 200 gate threads each ----
    int gbase;
    if (wid < 7)       gbase = 0;
    else if (wid < 14) gbase = 224;
    else               gbase = 448;
    const int gi = tid - gbase;
    const bool isGate = (gi < 200);
    const int j  = gi >> 2;
    const int ks = gi & 3;
    const unsigned qmask = 0xFu << (lane & ~3);

    float bz[4] = {0.f, 0.f, 0.f, 0.f};
    if (isGate) {
        const float *bi, *bh;
        if (wid < 7)       { bi = bih1; bh = bhh1; }
        else if (wid < 14) { bi = bih2; bh = bhh2; }
        else               { bi = bih3; bh = bhh3; }
#pragma unroll
        for (int g = 0; g < 4; g++)
            bz[g] = bi[g * HID + j] + bh[g * HID + j];
    }
    float ca = 0.f, cb = 0.f;

    const int sp_i = gi - 200;            // G1 spares: gi 200-223 (24 threads)
    __syncthreads();   // weights + v init visible

    for (int ph = 0; ph < T_STEPS + 2; ph++) {
        const int p = ph & 1, q = p ^ 1;

        if (wid < 7) {              // G1: layer1 @ t=ph (+ x prefetch)
            if (isGate) {
                if (ph < T_STEPS)
                    layer_phase<14, true>(sh, sh + W1_OFF,
                                          sh + V1_OFF + p * V1B,
                                          j, ks, qmask, bz, ca, cb,
                                          V1_OFF + q * V1B + (6 + j) * 8,
                                          V2_OFF + q * V2B + j * 8);
            } else {
                if (ph + 1 < T_STEPS) {
#pragma unroll
                    for (int r = 0; r < 2; r++) {
                        int s0 = sp_i + 24 * r;
                        if (s0 < NB * IN_DIM) {
                            int bb = s0 / IN_DIM, dd = s0 - bb * IN_DIM;
                            if (bb < cnt)
                                sh[V1_OFF + q * V1B + dd * 8 + bb] =
                                    x[(size_t)(b0 + bb) * T_STEPS * IN_DIM
                                      + (ph + 1) * IN_DIM + dd];
                        }
                    }
                }
            }
            asm volatile("bar.sync 1, 448;" ::: "memory");
        } else if (wid < 14) {      // G2: layer2 @ t=ph-1
            if (isGate && ph >= 1 && ph <= T_STEPS)
                layer_phase<25, true>(sh, sh + W2_OFF,
                                      sh + V2_OFF + p * V2B,
                                      j, ks, qmask, bz, ca, cb,
                                      V2_OFF + q * V2B + (50 + j) * 8,
                                      V3_OFF + q * V2B + j * 8);
            asm volatile("bar.sync 1, 448;" ::: "memory");
            asm volatile("bar.sync 2, 448;" ::: "memory");
        } else {                    // G3: layer3 @ t=ph-2
            if (isGate && ph >= 2)
                layer_phase<25, false>(sh, sh + W3_OFF,
                                       sh + V3_OFF + p * V2B,
                                       j, ks, qmask, bz, ca, cb,
                                       V3_OFF + q * V2B + (50 + j) * 8, 0);
            asm volatile("bar.sync 2, 448;" ::: "memory");
        }
    }
    __syncthreads();

    // FC: h3(511) computed at ph=513 -> parity q=0; row 50+j, column b
    if (tid < cnt) {
        float a = fcb[0];
#pragma unroll
        for (int jj = 0; jj < HID; jj++)
            a += fcW[jj] * sh[V3_OFF + (50 + jj) * 8 + tid];
        out[b0 + tid] = a;
    }
}

extern "C" void kernel_launch(void* const* d_in, const int* in_sizes, int n_in,
                              void* d_out, int out_size) {
    const float* x    = (const float*)d_in[0];
    const float* Wih1 = (const float*)d_in[1];
    const float* Whh1 = (const float*)d_in[2];
    const float* bih1 = (const float*)d_in[3];
    const float* bhh1 = (const float*)d_in[4];
    const float* Wih2 = (const float*)d_in[5];
    const float* Whh2 = (const float*)d_in[6];
    const float* bih2 = (const float*)d_in[7];
    const float* bhh2 = (const float*)d_in[8];
    const float* Wih3 = (const float*)d_in[9];
    const float* Whh3 = (const float*)d_in[10];
    const float* bih3 = (const float*)d_in[11];
    const float* bhh3 = (const float*)d_in[12];
    const float* fcW  = (const float*)d_in[13];
    const float* fcb  = (const float*)d_in[14];

    size_t shbytes = (size_t)SH_FLOATS * sizeof(float);
    cudaFuncSetAttribute(lstm3_pipe_kernel,
                         cudaFuncAttributeMaxDynamicSharedMemorySize,
                         (int)shbytes);
    lstm3_pipe_kernel<<<GRID, NTHREADS, shbytes>>>(
        x, Wih1, Whh1, bih1, bhh1, Wih2, Whh2, bih2, bhh2,
        Wih3, Whh3, bih3, bhh3, fcW, fcb, (float*)d_out);
}

// round 14
// speedup vs baseline: 1.1463x; 1.0354x over previous
#include <cuda_runtime.h>

// 3-layer LSTM (IN=5, H=50) + FC(50->1), B=1024, T=512.
// v13 = v10 (layer-pipelined, warp-pure, batch-packed f32x2 accs, pairwise
// named barriers) + PARTIAL REGISTER-CACHING OF WEIGHTS:
// each gate thread's weight slice is invariant across all 512 phases, so
// the first NC k-iterations' weights (G1: 8 of 28, G2/G3: 10 of 25 = 40
// floats) are loaded into registers once and reused every phase. This cuts
// the per-phase smem weight re-read (204.8 KB -> 128 KB, the dominant LDS
// crossbar term) by 37% and frees issue slots.

#define T_STEPS   512
#define IN_DIM    5
#define HID       50
#define NB        7
#define NTHREADS  576
#define GRID      148
#define W1ROW     208
#define W2ROW     200
#define NC1       8            // cached k-iters for L1 (of 28)
#define NCH       10           // cached k-iters for L2/L3 (of 25)

// smem offsets (floats)
enum {
    W1_OFF = 0,                 // 56 rows * 208 = 11648
    W2_OFF = 11648,             // 100 * 200 = 20000
    W3_OFF = 31648,             // 20000
    V1_OFF = 51648,             // 2 bufs * 56 rows * 8  [x(0-4),pad5,h1(6-55)]
    V2_OFF = 52544,             // 2 bufs * 100 * 8      [h1,h2]
    V3_OFF = 54144,             // 1600                  [h2,h3]
    SH_FLOATS = 55744           // 222976 bytes
};
#define V1B 448
#define V2B 800

typedef unsigned long long ull;

__device__ __forceinline__ ull ffma2(ull a, ull b, ull c) {
    ull d;
    asm("fma.rn.f32x2 %0, %1, %2, %3;" : "=l"(d) : "l"(a), "l"(b), "l"(c));
    return d;
}
__device__ __forceinline__ ull add2(ull a, ull b) {
    ull d;
    asm("add.rn.f32x2 %0, %1, %2;" : "=l"(d) : "l"(a), "l"(b));
    return d;
}
__device__ __forceinline__ ull pack2(float w) {
    ull d;
    asm("mov.b64 %0, {%1, %1};" : "=l"(d) : "f"(w));
    return d;
}
__device__ __forceinline__ void unpk(ull a, float& lo, float& hi) {
    asm("mov.b64 {%0, %1}, %2;" : "=f"(lo), "=f"(hi) : "l"(a));
}
__device__ __forceinline__ float fast_ex2(float x) {
    float y; asm("ex2.approx.ftz.f32 %0, %1;" : "=f"(y) : "f"(x)); return y;
}
__device__ __forceinline__ float fast_rcp(float x) {
    float y; asm("rcp.approx.ftz.f32 %0, %1;" : "=f"(y) : "f"(x)); return y;
}
__device__ __forceinline__ float sigm(float x) {
    return fast_rcp(1.0f + fast_ex2(-1.4426950408889634f * x));
}
__device__ __forceinline__ float tanh_acc(float x) {
    float r = fast_rcp(1.0f + fast_ex2(-2.8853900817779268f * x));
    return r + r - 1.0f;
}

// Accumulate 4 gates x 4 batch-pairs over k = ks + STRIDE*i, i < NK.
// Iterations i < NC take weights from the register cache wc (constant
// indices after unrolling), the rest from smem.
template<int NK, int STRIDE, int WROW, int NC>
__device__ __forceinline__ void accum(const float* __restrict__ shw,
                                      const float* __restrict__ vrd,
                                      const float* __restrict__ wc,
                                      int j, int ks, ull acc[4][4]) {
#pragma unroll
    for (int g = 0; g < 4; g++)
#pragma unroll
        for (int bp = 0; bp < 4; bp++) acc[g][bp] = 0ull;

#pragma unroll
    for (int i = 0; i < NK; i++) {
        const int k = ks + STRIDE * i;
        float4 w;
        if (i < NC) {
            w.x = wc[4 * i];     w.y = wc[4 * i + 1];
            w.z = wc[4 * i + 2]; w.w = wc[4 * i + 3];
        } else {
            w = *reinterpret_cast<const float4*>(shw + k * WROW + 4 * j);
        }
        const ulonglong2 va = *reinterpret_cast<const ulonglong2*>(vrd + k * 8);
        const ulonglong2 vb = *reinterpret_cast<const ulonglong2*>(vrd + k * 8 + 4);
        ull w0 = pack2(w.x), w1 = pack2(w.y), w2 = pack2(w.z), w3 = pack2(w.w);
        acc[0][0] = ffma2(w0, va.x, acc[0][0]);
        acc[0][1] = ffma2(w0, va.y, acc[0][1]);
        acc[0][2] = ffma2(w0, vb.x, acc[0][2]);
        acc[0][3] = ffma2(w0, vb.y, acc[0][3]);
        acc[1][0] = ffma2(w1, va.x, acc[1][0]);
        acc[1][1] = ffma2(w1, va.y, acc[1][1]);
        acc[1][2] = ffma2(w1, vb.x, acc[1][2]);
        acc[1][3] = ffma2(w1, vb.y, acc[1][3]);
        acc[2][0] = ffma2(w2, va.x, acc[2][0]);
        acc[2][1] = ffma2(w2, va.y, acc[2][1]);
        acc[2][2] = ffma2(w2, vb.x, acc[2][2]);
        acc[2][3] = ffma2(w2, vb.y, acc[2][3]);
        acc[3][0] = ffma2(w3, va.x, acc[3][0]);
        acc[3][1] = ffma2(w3, va.y, acc[3][1]);
        acc[3][2] = ffma2(w3, vb.x, acc[3][2]);
        acc[3][3] = ffma2(w3, vb.y, acc[3][3]);
    }
}

// ---- L2/L3 phase: 4-way K-split, payload-halving ull butterfly ----
template<bool HAS2>
__device__ __forceinline__ void layer_hid_phase(float* sh,
                                                const float* __restrict__ shw,
                                                const float* __restrict__ vrd,
                                                const float* __restrict__ wc,
                                                int j, int ks, unsigned qmask,
                                                const float bz[4],
                                                float& ca, float& cb,
                                                int wr1, int wr2) {
    ull acc[4][4];
    accum<25, 4, W2ROW, NCH>(shw, vrd, wc, j, ks, acc);

    const bool k1 = (ks & 2) != 0;
    const bool k0 = (ks & 1) != 0;
    float ta[4], tb[4];
#pragma unroll
    for (int g = 0; g < 4; g++) {
        ull s0 = k1 ? acc[g][0] : acc[g][2];
        ull s1 = k1 ? acc[g][1] : acc[g][3];
        ull K0 = k1 ? acc[g][2] : acc[g][0];
        ull K1 = k1 ? acc[g][3] : acc[g][1];
        ull m0 = add2(K0, __shfl_xor_sync(qmask, s0, 2));
        ull m1 = add2(K1, __shfl_xor_sync(qmask, s1, 2));
        ull s  = k0 ? m0 : m1;
        ull K  = k0 ? m1 : m0;
        ull tot = add2(K, __shfl_xor_sync(qmask, s, 1));
        float lo, hi; unpk(tot, lo, hi);
        ta[g] = lo + bz[g];
        tb[g] = hi + bz[g];
    }
    float ha, hb;
    {
        float iv = sigm(ta[0]), fv = sigm(ta[1]);
        float gv = tanh_acc(ta[2]), ov = sigm(ta[3]);
        ca = fv * ca + iv * gv;
        ha = ov * tanh_acc(ca);
    }
    {
        float iv = sigm(tb[0]), fv = sigm(tb[1]);
        float gv = tanh_acc(tb[2]), ov = sigm(tb[3]);
        cb = fv * cb + iv * gv;
        hb = ov * tanh_acc(cb);
    }
    float2 hh = make_float2(ha, hb);
    *reinterpret_cast<float2*>(sh + wr1 + 2 * ks) = hh;
    if (HAS2) *reinterpret_cast<float2*>(sh + wr2 + 2 * ks) = hh;
}

// ---- L1 phase: 2-way K-split, 1-round butterfly, 4 batches/thread ----
__device__ __forceinline__ void layer1_phase(float* sh, int p, int q, int j,
                                             int ks, unsigned pmask,
                                             const float* __restrict__ wc,
                                             const float bz[4], float c1[4]) {
    ull acc[4][4];
    accum<28, 2, W1ROW, NC1>(sh + W1_OFF, sh + V1_OFF + p * V1B, wc, j, ks, acc);

    const bool kb = (ks != 0);
    float t0[4], t1[4], t2[4], t3[4];
#pragma unroll
    for (int g = 0; g < 4; g++) {
        ull s0 = kb ? acc[g][0] : acc[g][2];
        ull s1 = kb ? acc[g][1] : acc[g][3];
        ull K0 = kb ? acc[g][2] : acc[g][0];
        ull K1 = kb ? acc[g][3] : acc[g][1];
        ull m0 = add2(K0, __shfl_xor_sync(pmask, s0, 1));
        ull m1 = add2(K1, __shfl_xor_sync(pmask, s1, 1));
        float a, b; unpk(m0, a, b);
        t0[g] = a + bz[g]; t1[g] = b + bz[g];
        unpk(m1, a, b);
        t2[g] = a + bz[g]; t3[g] = b + bz[g];
    }
    float h0, h1v, h2v, h3v;
    {
        float iv = sigm(t0[0]), fv = sigm(t0[1]);
        float gv = tanh_acc(t0[2]), ov = sigm(t0[3]);
        c1[0] = fv * c1[0] + iv * gv; h0 = ov * tanh_acc(c1[0]);
    }
    {
        float iv = sigm(t1[0]), fv = sigm(t1[1]);
        float gv = tanh_acc(t1[2]), ov = sigm(t1[3]);
        c1[1] = fv * c1[1] + iv * gv; h1v = ov * tanh_acc(c1[1]);
    }
    {
        float iv = sigm(t2[0]), fv = sigm(t2[1]);
        float gv = tanh_acc(t2[2]), ov = sigm(t2[3]);
        c1[2] = fv * c1[2] + iv * gv; h2v = ov * tanh_acc(c1[2]);
    }
    {
        float iv = sigm(t3[0]), fv = sigm(t3[1]);
        float gv = tanh_acc(t3[2]), ov = sigm(t3[3]);
        c1[3] = fv * c1[3] + iv * gv; h3v = ov * tanh_acc(c1[3]);
    }
    float4 hq = make_float4(h0, h1v, h2v, h3v);
    *reinterpret_cast<float4*>(sh + V1_OFF + q * V1B + (6 + j) * 8 + 4 * ks) = hq;
    *reinterpret_cast<float4*>(sh + V2_OFF + q * V2B + j * 8 + 4 * ks)       = hq;
}

__global__ void __launch_bounds__(NTHREADS, 1)
lstm3_pipe_kernel(const float* __restrict__ x,
                  const float* __restrict__ Wih1, const float* __restrict__ Whh1,
                  const float* __restrict__ bih1, const float* __restrict__ bhh1,
                  const float* __restrict__ Wih2, const float* __restrict__ Whh2,
                  const float* __restrict__ bih2, const float* __restrict__ bhh2,
                  const float* __restrict__ Wih3, const float* __restrict__ Whh3,
                  const float* __restrict__ bih3, const float* __restrict__ bhh3,
                  const float* __restrict__ fcW, const float* __restrict__ fcb,
                  float* __restrict__ out) {
    extern __shared__ float sh[];
    const int tid = threadIdx.x;
    const int bid = blockIdx.x;
    const int lane = tid & 31;
    const int wid = tid >> 5;

    int b0, cnt;
    if (bid < 136) { b0 = bid * 7;               cnt = 7; }
    else           { b0 = 952 + (bid - 136) * 6; cnt = 6; }

    // zero v buffers
    for (int i = V1_OFF + tid; i < SH_FLOATS; i += NTHREADS) sh[i] = 0.0f;

    // stage W1: [k][j*4+g]
    for (int idx = tid; idx < 200 * 56; idx += NTHREADS) {
        int gr = idx / 56, k = idx - gr * 56;
        int g = gr / 50, j = gr - g * 50;
        float v;
        if (k < IN_DIM)       v = Wih1[gr * IN_DIM + k];
        else if (k == IN_DIM) v = 0.0f;
        else                  v = Whh1[gr * HID + (k - 6)];
        sh[W1_OFF + k * W1ROW + j * 4 + g] = v;
    }
    for (int idx = tid; idx < 200 * 100; idx += NTHREADS) {
        int gr = idx / 100, k = idx - gr * 100;
        int g = gr / 50, j = gr - g * 50;
        float v = (k < HID) ? Wih2[gr * HID + k] : Whh2[gr * HID + (k - HID)];
        sh[W2_OFF + k * W2ROW + j * 4 + g] = v;
    }
    for (int idx = tid; idx < 200 * 100; idx += NTHREADS) {
        int gr = idx / 100, k = idx - gr * 100;
        int g = gr / 50, j = gr - g * 50;
        float v = (k < HID) ? Wih3[gr * HID + k] : Whh3[gr * HID + (k - HID)];
        sh[W3_OFF + k * W2ROW + j * 4 + g] = v;
    }
    // x(t=0)
    if (tid < NB * IN_DIM) {
        int b = tid / IN_DIM, d = tid - b * IN_DIM;
        if (b < cnt)
            sh[V1_OFF + d * 8 + b] = x[(size_t)(b0 + b) * T_STEPS * IN_DIM + d];
    }

    const bool isL1 = (tid < 100);
    const bool isSp = (tid >= 100 && tid < 128);
    const bool isL2 = (tid >= 128 && tid < 328);
    const bool isL3 = (tid >= 352 && tid < 552);

    int j = 0, ks = 0;
    if (isL1)      { j = tid >> 1;       ks = tid & 1; }
    else if (isL2) { int i2 = tid - 128; j = i2 >> 2; ks = i2 & 3; }
    else if (isL3) { int i3 = tid - 352; j = i3 >> 2; ks = i3 & 3; }

    const unsigned pmask = 0x3u << (lane & ~1);
    const unsigned qmask = 0xFu << (lane & ~3);

    float bz[4] = {0.f, 0.f, 0.f, 0.f};
    if (isL1) {
#pragma unroll
        for (int g = 0; g < 4; g++)
            bz[g] = bih1[g * HID + j] + bhh1[g * HID + j];
    } else if (isL2) {
#pragma unroll
        for (int g = 0; g < 4; g++)
            bz[g] = bih2[g * HID + j] + bhh2[g * HID + j];
    } else if (isL3) {
#pragma unroll
        for (int g = 0; g < 4; g++)
            bz[g] = bih3[g * HID + j] + bhh3[g * HID + j];
    }

    float c1[4] = {0.f, 0.f, 0.f, 0.f};
    float ca = 0.f, cb = 0.f;

    const int sp_i = tid - 100;
    __syncthreads();   // weights + v init visible to all

    // ---- fill per-thread weight register cache (invariant across phases) ----
    float wc[4 * NCH];   // G1 uses 4*NC1 <= 4*NCH entries
    if (isL1) {
#pragma unroll
        for (int i = 0; i < NC1; i++) {
            const int k = ks + 2 * i;
            const float4 w = *reinterpret_cast<const float4*>(
                sh + W1_OFF + k * W1ROW + 4 * j);
            wc[4 * i] = w.x; wc[4 * i + 1] = w.y;
            wc[4 * i + 2] = w.z; wc[4 * i + 3] = w.w;
        }
    } else if (isL2 || isL3) {
        const float* wb = sh + (isL2 ? W2_OFF : W3_OFF);
#pragma unroll
        for (int i = 0; i < NCH; i++) {
            const int k = ks + 4 * i;
            const float4 w = *reinterpret_cast<const float4*>(
                wb + k * W2ROW + 4 * j);
            wc[4 * i] = w.x; wc[4 * i + 1] = w.y;
            wc[4 * i + 2] = w.z; wc[4 * i + 3] = w.w;
        }
    }

    for (int ph = 0; ph < T_STEPS + 2; ph++) {
        const int p = ph & 1, q = p ^ 1;

        if (wid < 4) {              // G1: L1 + spares
            if (isL1) {
                if (ph < T_STEPS)
                    layer1_phase(sh, p, q, j, ks, pmask, wc, bz, c1);
            } else if (isSp) {
                if (ph + 1 < T_STEPS) {
#pragma unroll
                    for (int r = 0; r < 2; r++) {
                        int s0 = sp_i + 28 * r;
                        if (s0 < NB * IN_DIM) {
                            int bb = s0 / IN_DIM, dd = s0 - bb * IN_DIM;
                            if (bb < cnt)
                                sh[V1_OFF + q * V1B + dd * 8 + bb] =
                                    x[(size_t)(b0 + bb) * T_STEPS * IN_DIM
                                      + (ph + 1) * IN_DIM + dd];
                        }
                    }
                }
            }
            asm volatile("bar.sync 1, 352;" ::: "memory");
        } else if (wid < 11) {      // G2: L2
            if (isL2 && ph >= 1 && ph <= T_STEPS)
                layer_hid_phase<true>(sh, sh + W2_OFF,
                                      sh + V2_OFF + p * V2B, wc,
                                      j, ks, qmask, bz, ca, cb,
                                      V2_OFF + q * V2B + (50 + j) * 8,
                                      V3_OFF + q * V2B + j * 8);
            asm volatile("bar.sync 1, 352;" ::: "memory");
            asm volatile("bar.sync 2, 448;" ::: "memory");
        } else {                    // G3: L3
            if (isL3 && ph >= 2)
                layer_hid_phase<false>(sh, sh + W3_OFF,
                                       sh + V3_OFF + p * V2B, wc,
                                       j, ks, qmask, bz, ca, cb,
                                       V3_OFF + q * V2B + (50 + j) * 8, 0);
            asm volatile("bar.sync 2, 448;" ::: "memory");
        }
    }
    __syncthreads();

    // FC: h3(511) written at ph=513 -> buf q=0; row 50+j, column b
    if (tid < cnt) {
        float a = fcb[0];
#pragma unroll
        for (int jj = 0; jj < HID; jj++)
            a += fcW[jj] * sh[V3_OFF + (50 + jj) * 8 + tid];
        out[b0 + tid] = a;
    }
}

extern "C" void kernel_launch(void* const* d_in, const int* in_sizes, int n_in,
                              void* d_out, int out_size) {
    const float* x    = (const float*)d_in[0];
    const float* Wih1 = (const float*)d_in[1];
    const float* Whh1 = (const float*)d_in[2];
    const float* bih1 = (const float*)d_in[3];
    const float* bhh1 = (const float*)d_in[4];
    const float* Wih2 = (const float*)d_in[5];
    const float* Whh2 = (const float*)d_in[6];
    const float* bih2 = (const float*)d_in[7];
    const float* bhh2 = (const float*)d_in[8];
    const float* Wih3 = (const float*)d_in[9];
    const float* Whh3 = (const float*)d_in[10];
    const float* bih3 = (const float*)d_in[11];
    const float* bhh3 = (const float*)d_in[12];
    const float* fcW  = (const float*)d_in[13];
    const float* fcb  = (const float*)d_in[14];

    size_t shbytes = (size_t)SH_FLOATS * sizeof(float);
    cudaFuncSetAttribute(lstm3_pipe_kernel,
                         cudaFuncAttributeMaxDynamicSharedMemorySize,
                         (int)shbytes);
    lstm3_pipe_kernel<<<GRID, NTHREADS, shbytes>>>(
        x, Wih1, Whh1, bih1, bhh1, Wih2, Whh2, bih2, bhh2,
        Wih3, Whh3, bih3, bhh3, fcW, fcb, (float*)d_out);
}

// round 15
// speedup vs baseline: 1.1657x; 1.0169x over previous
#include <cuda_runtime.h>

// 3-layer LSTM (IN=5, H=50) + FC(50->1), B=1024, T=512.
// v14 = v13 with the weight register-cache SIZED TO FIT the 112-reg cap
// (576 threads): NCH 10->7, NC1 8->6. v13's 40-float cache partially
// spilled to local (ncu: L2=4.8%, regs capped at 96), contaminating the
// experiment. Demand now ~105 regs <= 112. Per-phase smem weight re-read
// drops 204.8 KB -> ~148 KB with zero local traffic.

#define T_STEPS   512
#define IN_DIM    5
#define HID       50
#define NB        7
#define NTHREADS  576
#define GRID      148
#define W1ROW     208
#define W2ROW     200
#define NC1       6            // cached k-iters for L1 (of 28)
#define NCH       7            // cached k-iters for L2/L3 (of 25)

// smem offsets (floats)
enum {
    W1_OFF = 0,                 // 56 rows * 208 = 11648
    W2_OFF = 11648,             // 100 * 200 = 20000
    W3_OFF = 31648,             // 20000
    V1_OFF = 51648,             // 2 bufs * 56 rows * 8  [x(0-4),pad5,h1(6-55)]
    V2_OFF = 52544,             // 2 bufs * 100 * 8      [h1,h2]
    V3_OFF = 54144,             // 1600                  [h2,h3]
    SH_FLOATS = 55744           // 222976 bytes
};
#define V1B 448
#define V2B 800

typedef unsigned long long ull;

__device__ __forceinline__ ull ffma2(ull a, ull b, ull c) {
    ull d;
    asm("fma.rn.f32x2 %0, %1, %2, %3;" : "=l"(d) : "l"(a), "l"(b), "l"(c));
    return d;
}
__device__ __forceinline__ ull add2(ull a, ull b) {
    ull d;
    asm("add.rn.f32x2 %0, %1, %2;" : "=l"(d) : "l"(a), "l"(b));
    return d;
}
__device__ __forceinline__ ull pack2(float w) {
    ull d;
    asm("mov.b64 %0, {%1, %1};" : "=l"(d) : "f"(w));
    return d;
}
__device__ __forceinline__ void unpk(ull a, float& lo, float& hi) {
    asm("mov.b64 {%0, %1}, %2;" : "=f"(lo), "=f"(hi) : "l"(a));
}
__device__ __forceinline__ float fast_ex2(float x) {
    float y; asm("ex2.approx.ftz.f32 %0, %1;" : "=f"(y) : "f"(x)); return y;
}
__device__ __forceinline__ float fast_rcp(float x) {
    float y; asm("rcp.approx.ftz.f32 %0, %1;" : "=f"(y) : "f"(x)); return y;
}
__device__ __forceinline__ float sigm(float x) {
    return fast_rcp(1.0f + fast_ex2(-1.4426950408889634f * x));
}
__device__ __forceinline__ float tanh_acc(float x) {
    float r = fast_rcp(1.0f + fast_ex2(-2.8853900817779268f * x));
    return r + r - 1.0f;
}

// Accumulate 4 gates x 4 batch-pairs over k = ks + STRIDE*i, i < NK.
// Iterations i < NC take weights from the register cache wc.
template<int NK, int STRIDE, int WROW, int NC>
__device__ __forceinline__ void accum(const float* __restrict__ shw,
                                      const float* __restrict__ vrd,
                                      const float* __restrict__ wc,
                                      int j, int ks, ull acc[4][4]) {
#pragma unroll
    for (int g = 0; g < 4; g++)
#pragma unroll
        for (int bp = 0; bp < 4; bp++) acc[g][bp] = 0ull;

#pragma unroll
    for (int i = 0; i < NK; i++) {
        const int k = ks + STRIDE * i;
        float4 w;
        if (i < NC) {
            w.x = wc[4 * i];     w.y = wc[4 * i + 1];
            w.z = wc[4 * i + 2]; w.w = wc[4 * i + 3];
        } else {
            w = *reinterpret_cast<const float4*>(shw + k * WROW + 4 * j);
        }
        const ulonglong2 va = *reinterpret_cast<const ulonglong2*>(vrd + k * 8);
        const ulonglong2 vb = *reinterpret_cast<const ulonglong2*>(vrd + k * 8 + 4);
        ull w0 = pack2(w.x), w1 = pack2(w.y), w2 = pack2(w.z), w3 = pack2(w.w);
        acc[0][0] = ffma2(w0, va.x, acc[0][0]);
        acc[0][1] = ffma2(w0, va.y, acc[0][1]);
        acc[0][2] = ffma2(w0, vb.x, acc[0][2]);
        acc[0][3] = ffma2(w0, vb.y, acc[0][3]);
        acc[1][0] = ffma2(w1, va.x, acc[1][0]);
        acc[1][1] = ffma2(w1, va.y, acc[1][1]);
        acc[1][2] = ffma2(w1, vb.x, acc[1][2]);
        acc[1][3] = ffma2(w1, vb.y, acc[1][3]);
        acc[2][0] = ffma2(w2, va.x, acc[2][0]);
        acc[2][1] = ffma2(w2, va.y, acc[2][1]);
        acc[2][2] = ffma2(w2, vb.x, acc[2][2]);
        acc[2][3] = ffma2(w2, vb.y, acc[2][3]);
        acc[3][0] = ffma2(w3, va.x, acc[3][0]);
        acc[3][1] = ffma2(w3, va.y, acc[3][1]);
        acc[3][2] = ffma2(w3, vb.x, acc[3][2]);
        acc[3][3] = ffma2(w3, vb.y, acc[3][3]);
    }
}

// ---- L2/L3 phase: 4-way K-split, payload-halving ull butterfly ----
template<bool HAS2>
__device__ __forceinline__ void layer_hid_phase(float* sh,
                                                const float* __restrict__ shw,
                                                const float* __restrict__ vrd,
                                                const float* __restrict__ wc,
                                                int j, int ks, unsigned qmask,
                                                const float bz[4],
                                                float& ca, float& cb,
                                                int wr1, int wr2) {
    ull acc[4][4];
    accum<25, 4, W2ROW, NCH>(shw, vrd, wc, j, ks, acc);

    const bool k1 = (ks & 2) != 0;
    const bool k0 = (ks & 1) != 0;
    float ta[4], tb[4];
#pragma unroll
    for (int g = 0; g < 4; g++) {
        ull s0 = k1 ? acc[g][0] : acc[g][2];
        ull s1 = k1 ? acc[g][1] : acc[g][3];
        ull K0 = k1 ? acc[g][2] : acc[g][0];
        ull K1 = k1 ? acc[g][3] : acc[g][1];
        ull m0 = add2(K0, __shfl_xor_sync(qmask, s0, 2));
        ull m1 = add2(K1, __shfl_xor_sync(qmask, s1, 2));
        ull s  = k0 ? m0 : m1;
        ull K  = k0 ? m1 : m0;
        ull tot = add2(K, __shfl_xor_sync(qmask, s, 1));
        float lo, hi; unpk(tot, lo, hi);
        ta[g] = lo + bz[g];
        tb[g] = hi + bz[g];
    }
    float ha, hb;
    {
        float iv = sigm(ta[0]), fv = sigm(ta[1]);
        float gv = tanh_acc(ta[2]), ov = sigm(ta[3]);
        ca = fv * ca + iv * gv;
        ha = ov * tanh_acc(ca);
    }
    {
        float iv = sigm(tb[0]), fv = sigm(tb[1]);
        float gv = tanh_acc(tb[2]), ov = sigm(tb[3]);
        cb = fv * cb + iv * gv;
        hb = ov * tanh_acc(cb);
    }
    float2 hh = make_float2(ha, hb);
    *reinterpret_cast<float2*>(sh + wr1 + 2 * ks) = hh;
    if (HAS2) *reinterpret_cast<float2*>(sh + wr2 + 2 * ks) = hh;
}

// ---- L1 phase: 2-way K-split, 1-round butterfly, 4 batches/thread ----
__device__ __forceinline__ void layer1_phase(float* sh, int p, int q, int j,
                                             int ks, unsigned pmask,
                                             const float* __restrict__ wc,
                                             const float bz[4], float c1[4]) {
    ull acc[4][4];
    accum<28, 2, W1ROW, NC1>(sh + W1_OFF, sh + V1_OFF + p * V1B, wc, j, ks, acc);

    const bool kb = (ks != 0);
    float t0[4], t1[4], t2[4], t3[4];
#pragma unroll
    for (int g = 0; g < 4; g++) {
        ull s0 = kb ? acc[g][0] : acc[g][2];
        ull s1 = kb ? acc[g][1] : acc[g][3];
        ull K0 = kb ? acc[g][2] : acc[g][0];
        ull K1 = kb ? acc[g][3] : acc[g][1];
        ull m0 = add2(K0, __shfl_xor_sync(pmask, s0, 1));
        ull m1 = add2(K1, __shfl_xor_sync(pmask, s1, 1));
        float a, b; unpk(m0, a, b);
        t0[g] = a + bz[g]; t1[g] = b + bz[g];
        unpk(m1, a, b);
        t2[g] = a + bz[g]; t3[g] = b + bz[g];
    }
    float h0, h1v, h2v, h3v;
    {
        float iv = sigm(t0[0]), fv = sigm(t0[1]);
        float gv = tanh_acc(t0[2]), ov = sigm(t0[3]);
        c1[0] = fv * c1[0] + iv * gv; h0 = ov * tanh_acc(c1[0]);
    }
    {
        float iv = sigm(t1[0]), fv = sigm(t1[1]);
        float gv = tanh_acc(t1[2]), ov = sigm(t1[3]);
        c1[1] = fv * c1[1] + iv * gv; h1v = ov * tanh_acc(c1[1]);
    }
    {
        float iv = sigm(t2[0]), fv = sigm(t2[1]);
        float gv = tanh_acc(t2[2]), ov = sigm(t2[3]);
        c1[2] = fv * c1[2] + iv * gv; h2v = ov * tanh_acc(c1[2]);
    }
    {
        float iv = sigm(t3[0]), fv = sigm(t3[1]);
        float gv = tanh_acc(t3[2]), ov = sigm(t3[3]);
        c1[3] = fv * c1[3] + iv * gv; h3v = ov * tanh_acc(c1[3]);
    }
    float4 hq = make_float4(h0, h1v, h2v, h3v);
    *reinterpret_cast<float4*>(sh + V1_OFF + q * V1B + (6 + j) * 8 + 4 * ks) = hq;
    *reinterpret_cast<float4*>(sh + V2_OFF + q * V2B + j * 8 + 4 * ks)       = hq;
}

__global__ void __launch_bounds__(NTHREADS, 1)
lstm3_pipe_kernel(const float* __restrict__ x,
                  const float* __restrict__ Wih1, const float* __restrict__ Whh1,
                  const float* __restrict__ bih1, const float* __restrict__ bhh1,
                  const float* __restrict__ Wih2, const float* __restrict__ Whh2,
                  const float* __restrict__ bih2, const float* __restrict__ bhh2,
                  const float* __restrict__ Wih3, const float* __restrict__ Whh3,
                  const float* __restrict__ bih3, const float* __restrict__ bhh3,
                  const float* __restrict__ fcW, const float* __restrict__ fcb,
                  float* __restrict__ out) {
    extern __shared__ float sh[];
    const int tid = threadIdx.x;
    const int bid = blockIdx.x;
    const int lane = tid & 31;
    const int wid = tid >> 5;

    int b0, cnt;
    if (bid < 136) { b0 = bid * 7;               cnt = 7; }
    else           { b0 = 952 + (bid - 136) * 6; cnt = 6; }

    // zero v buffers
    for (int i = V1_OFF + tid; i < SH_FLOATS; i += NTHREADS) sh[i] = 0.0f;

    // stage W1: [k][j*4+g]
    for (int idx = tid; idx < 200 * 56; idx += NTHREADS) {
        int gr = idx / 56, k = idx - gr * 56;
        int g = gr / 50, j = gr - g * 50;
        float v;
        if (k < IN_DIM)       v = Wih1[gr * IN_DIM + k];
        else if (k == IN_DIM) v = 0.0f;
        else                  v = Whh1[gr * HID + (k - 6)];
        sh[W1_OFF + k * W1ROW + j * 4 + g] = v;
    }
    for (int idx = tid; idx < 200 * 100; idx += NTHREADS) {
        int gr = idx / 100, k = idx - gr * 100;
        int g = gr / 50, j = gr - g * 50;
        float v = (k < HID) ? Wih2[gr * HID + k] : Whh2[gr * HID + (k - HID)];
        sh[W2_OFF + k * W2ROW + j * 4 + g] = v;
    }
    for (int idx = tid; idx < 200 * 100; idx += NTHREADS) {
        int gr = idx / 100, k = idx - gr * 100;
        int g = gr / 50, j = gr - g * 50;
        float v = (k < HID) ? Wih3[gr * HID + k] : Whh3[gr * HID + (k - HID)];
        sh[W3_OFF + k * W2ROW + j * 4 + g] = v;
    }
    // x(t=0)
    if (tid < NB * IN_DIM) {
        int b = tid / IN_DIM, d = tid - b * IN_DIM;
        if (b < cnt)
            sh[V1_OFF + d * 8 + b] = x[(size_t)(b0 + b) * T_STEPS * IN_DIM + d];
    }

    const bool isL1 = (tid < 100);
    const bool isSp = (tid >= 100 && tid < 128);
    const bool isL2 = (tid >= 128 && tid < 328);
    const bool isL3 = (tid >= 352 && tid < 552);

    int j = 0, ks = 0;
    if (isL1)      { j = tid >> 1;       ks = tid & 1; }
    else if (isL2) { int i2 = tid - 128; j = i2 >> 2; ks = i2 & 3; }
    else if (isL3) { int i3 = tid - 352; j = i3 >> 2; ks = i3 & 3; }

    const unsigned pmask = 0x3u << (lane & ~1);
    const unsigned qmask = 0xFu << (lane & ~3);

    float bz[4] = {0.f, 0.f, 0.f, 0.f};
    if (isL1) {
#pragma unroll
        for (int g = 0; g < 4; g++)
            bz[g] = bih1[g * HID + j] + bhh1[g * HID + j];
    } else if (isL2) {
#pragma unroll
        for (int g = 0; g < 4; g++)
            bz[g] = bih2[g * HID + j] + bhh2[g * HID + j];
    } else if (isL3) {
#pragma unroll
        for (int g = 0; g < 4; g++)
            bz[g] = bih3[g * HID + j] + bhh3[g * HID + j];
    }

    float c1[4] = {0.f, 0.f, 0.f, 0.f};
    float ca = 0.f, cb = 0.f;

    const int sp_i = tid - 100;
    __syncthreads();   // weights + v init visible to all

    // ---- per-thread weight register cache (fits the 112-reg cap now) ----
    float wc[4 * NCH];   // G1 uses 4*NC1 <= 4*NCH entries
    if (isL1) {
#pragma unroll
        for (int i = 0; i < NC1; i++) {
            const int k = ks + 2 * i;
            const float4 w = *reinterpret_cast<const float4*>(
                sh + W1_OFF + k * W1ROW + 4 * j);
            wc[4 * i] = w.x; wc[4 * i + 1] = w.y;
            wc[4 * i + 2] = w.z; wc[4 * i + 3] = w.w;
        }
    } else if (isL2 || isL3) {
        const float* wb = sh + (isL2 ? W2_OFF : W3_OFF);
#pragma unroll
        for (int i = 0; i < NCH; i++) {
            const int k = ks + 4 * i;
            const float4 w = *reinterpret_cast<const float4*>(
                wb + k * W2ROW + 4 * j);
            wc[4 * i] = w.x; wc[4 * i + 1] = w.y;
            wc[4 * i + 2] = w.z; wc[4 * i + 3] = w.w;
        }
    }

    for (int ph = 0; ph < T_STEPS + 2; ph++) {
        const int p = ph & 1, q = p ^ 1;

        if (wid < 4) {              // G1: L1 + spares
            if (isL1) {
                if (ph < T_STEPS)
                    layer1_phase(sh, p, q, j, ks, pmask, wc, bz, c1);
            } else if (isSp) {
                if (ph + 1 < T_STEPS) {
#pragma unroll
                    for (int r = 0; r < 2; r++) {
                        int s0 = sp_i + 28 * r;
                        if (s0 < NB * IN_DIM) {
                            int bb = s0 / IN_DIM, dd = s0 - bb * IN_DIM;
                            if (bb < cnt)
                                sh[V1_OFF + q * V1B + dd * 8 + bb] =
                                    x[(size_t)(b0 + bb) * T_STEPS * IN_DIM
                                      + (ph + 1) * IN_DIM + dd];
                        }
                    }
                }
            }
            asm volatile("bar.sync 1, 352;" ::: "memory");
        } else if (wid < 11) {      // G2: L2
            if (isL2 && ph >= 1 && ph <= T_STEPS)
                layer_hid_phase<true>(sh, sh + W2_OFF,
                                      sh + V2_OFF + p * V2B, wc,
                                      j, ks, qmask, bz, ca, cb,
                                      V2_OFF + q * V2B + (50 + j) * 8,
                                      V3_OFF + q * V2B + j * 8);
            asm volatile("bar.sync 1, 352;" ::: "memory");
            asm volatile("bar.sync 2, 448;" ::: "memory");
        } else {                    // G3: L3
            if (isL3 && ph >= 2)
                layer_hid_phase<false>(sh, sh + W3_OFF,
                                       sh + V3_OFF + p * V2B, wc,
                                       j, ks, qmask, bz, ca, cb,
                                       V3_OFF + q * V2B + (50 + j) * 8, 0);
            asm volatile("bar.sync 2, 448;" ::: "memory");
        }
    }
    __syncthreads();

    // FC: h3(511) written at ph=513 -> buf q=0; row 50+j, column b
    if (tid < cnt) {
        float a = fcb[0];
#pragma unroll
        for (int jj = 0; jj < HID; jj++)
            a += fcW[jj] * sh[V3_OFF + (50 + jj) * 8 + tid];
        out[b0 + tid] = a;
    }
}

extern "C" void kernel_launch(void* const* d_in, const int* in_sizes, int n_in,
                              void* d_out, int out_size) {
    const float* x    = (const float*)d_in[0];
    const float* Wih1 = (const float*)d_in[1];
    const float* Whh1 = (const float*)d_in[2];
    const float* bih1 = (const float*)d_in[3];
    const float* bhh1 = (const float*)d_in[4];
    const float* Wih2 = (const float*)d_in[5];
    const float* Whh2 = (const float*)d_in[6];
    const float* bih2 = (const float*)d_in[7];
    const float* bhh2 = (const float*)d_in[8];
    const float* Wih3 = (const float*)d_in[9];
    const float* Whh3 = (const float*)d_in[10];
    const float* bih3 = (const float*)d_in[11];
    const float* bhh3 = (const float*)d_in[12];
    const float* fcW  = (const float*)d_in[13];
    const float* fcb  = (const float*)d_in[14];

    size_t shbytes = (size_t)SH_FLOATS * sizeof(float);
    cudaFuncSetAttribute(lstm3_pipe_kernel,
                         cudaFuncAttributeMaxDynamicSharedMemorySize,
                         (int)shbytes);
    lstm3_pipe_kernel<<<GRID, NTHREADS, shbytes>>>(
        x, Wih1, Whh1, bih1, bhh1, Wih2, Whh2, bih2, bhh2,
        Wih3, Whh3, bih3, bhh3, fcW, fcb, (float*)d_out);
}